// round 1
// baseline (speedup 1.0000x reference)
#include <cuda_runtime.h>

// warp3D: out[b,c,z,y,x] = trilinear gather of I at (x+fx, y+fy, z+fz)
// Shapes fixed by the problem: B=2, C=2, D=160, H=192, W=224, fp32.

#define Wd 224
#define Hd 192
#define Dd 160
#define Bd 2
#define Cd 2
#define HWd (Hd * Wd)          // 43008
#define DHWd (Dd * HWd)        // 6881280

__global__ __launch_bounds__(Wd) void warp3d_kernel(
    const float* __restrict__ I,
    const float* __restrict__ flow,
    float* __restrict__ out)
{
    const int x = threadIdx.x;     // 0..223
    const int y = blockIdx.x;      // 0..191
    const int z = blockIdx.y;      // 0..159
    const int b = blockIdx.z;      // 0..1

    const long s = (long)z * HWd + (long)y * Wd + x;

    // flow[b, ch, z, y, x]
    const float* __restrict__ fb = flow + (long)b * 3 * DHWd + s;
    const float fx = __ldg(fb);
    const float fy = __ldg(fb + DHWd);
    const float fz = __ldg(fb + 2L * DHWd);

    const float xs = fx + (float)x;
    const float ys = fy + (float)y;
    const float zs = fz + (float)z;

    int x0 = (int)floorf(xs);
    int y0 = (int)floorf(ys);
    int z0 = (int)floorf(zs);
    // NOTE: order matters — x1 from UNclamped x0+1, then clamp both.
    int x1 = min(max(x0 + 1, 0), Wd - 1);
    int y1 = min(max(y0 + 1, 0), Hd - 1);
    int z1 = min(max(z0 + 1, 0), Dd - 1);
    x0 = min(max(x0, 0), Wd - 1);
    y0 = min(max(y0, 0), Hd - 1);
    z0 = min(max(z0, 0), Dd - 1);

    // Weights use the CLAMPED upper corner (matches reference).
    const float dx = (float)x1 - xs;
    const float dy = (float)y1 - ys;
    const float dz = (float)z1 - zs;
    const float ex = 1.0f - dx;
    const float ey = 1.0f - dy;
    const float ez = 1.0f - dz;

    // Bilinear weights in (x,y) plane:
    //   corner (y0,x0): dx*dy   (y1,x0): dx*ey   (y0,x1): ex*dy   (y1,x1): ex*ey
    const float w00 = dx * dy;
    const float w10 = dx * ey;
    const float w01 = ex * dy;
    const float w11 = ex * ey;

    const int r00 = z0 * HWd + y0 * Wd;   // z0,y0
    const int r10 = z0 * HWd + y1 * Wd;   // z0,y1
    const int r01 = z1 * HWd + y0 * Wd;   // z1,y0
    const int r11 = z1 * HWd + y1 * Wd;   // z1,y1

    const float* __restrict__ Ib = I + (long)b * Cd * DHWd;

    float res[Cd];
#pragma unroll
    for (int c = 0; c < Cd; ++c) {
        const float* __restrict__ Ic = Ib + (long)c * DHWd;
        // z0 plane bilinear
        float p0 = w00 * __ldg(Ic + r00 + x0)
                 + w10 * __ldg(Ic + r10 + x0)
                 + w01 * __ldg(Ic + r00 + x1)
                 + w11 * __ldg(Ic + r10 + x1);
        // z1 plane bilinear
        float p1 = w00 * __ldg(Ic + r01 + x0)
                 + w10 * __ldg(Ic + r11 + x0)
                 + w01 * __ldg(Ic + r01 + x1)
                 + w11 * __ldg(Ic + r11 + x1);
        res[c] = dz * p0 + ez * p1;
    }

    float* __restrict__ ob = out + (long)b * Cd * DHWd + s;
#pragma unroll
    for (int c = 0; c < Cd; ++c)
        ob[(long)c * DHWd] = res[c];
}

extern "C" void kernel_launch(void* const* d_in, const int* in_sizes, int n_in,
                              void* d_out, int out_size)
{
    const float* I    = (const float*)d_in[0];
    const float* flow = (const float*)d_in[1];
    float* out        = (float*)d_out;

    dim3 block(Wd, 1, 1);        // 224 = 7 warps
    dim3 grid(Hd, Dd, Bd);       // 192 x 160 x 2 blocks
    warp3d_kernel<<<grid, block>>>(I, flow, out);
}